// round 1
// baseline (speedup 1.0000x reference)
#include <cuda_runtime.h>
#include <math.h>
#include <stdint.h>

// Problem constants
#define BB  8
#define LL  1024
#define DD  1024
#define HH  16
#define DHH 64

typedef unsigned long long u64;
union F2 { u64 u; float2 f; };

// Scratch (device globals: allocation-free per harness rules)
__device__ float g_q[BB * LL * DD];
__device__ float g_k[BB * LL * DD];
__device__ float g_v[BB * LL * DD];
__device__ float g_a[BB * LL * DD];

// ---- packed f32x2 helpers (sm_100+) ----
__device__ __forceinline__ u64 pack2(float x, float y) {
    u64 r;
    asm("mov.b64 %0, {%1, %2};" : "=l"(r) : "f"(x), "f"(y));
    return r;
}
__device__ __forceinline__ void fma2(u64& d, u64 a, u64 b) {
    asm("fma.rn.f32x2 %0, %1, %2, %3;" : "=l"(d) : "l"(a), "l"(b), "l"(d));
}
__device__ __forceinline__ void mul2(u64& d, u64 a) {
    asm("mul.rn.f32x2 %0, %1, %2;" : "=l"(d) : "l"(d), "l"(a));
}

// ============================================================
// GEMM (NT): C[M,1024] = A[M,1024] * B[1024,1024]^T
// A row-major [M,K], B row-major [N,K] (both K contiguous).
// 128x128x8 tiles, 256 threads, 8x8 microtile, f32x2 accumulate.
// ============================================================
__global__ __launch_bounds__(256, 2) void gemm_nt_kernel(
    const float* __restrict__ A, const float* __restrict__ B,
    float* __restrict__ C, int M)
{
    const int K = 1024, N = 1024;
    __shared__ float As[8][128];
    __shared__ float Bs[8][128];

    const int tid = threadIdx.x;
    const int m0 = blockIdx.y * 128;
    const int n0 = blockIdx.x * 128;
    const int ty = tid >> 4;       // 0..15
    const int tx = tid & 15;       // 0..15
    const int lr = tid >> 1;       // 0..127 (load row)
    const int lc = (tid & 1) * 4;  // 0 or 4 (load col base)

    const float* Ap = A + (size_t)(m0 + lr) * K + lc;
    const float* Bp = B + (size_t)(n0 + lr) * K + lc;

    F2 acc[8][4];
#pragma unroll
    for (int i = 0; i < 8; i++)
#pragma unroll
        for (int j = 0; j < 4; j++) acc[i][j].u = 0ull;

    for (int k0 = 0; k0 < K; k0 += 8) {
        float4 av = *(const float4*)(Ap + k0);
        float4 bv = *(const float4*)(Bp + k0);
        As[lc + 0][lr] = av.x; As[lc + 1][lr] = av.y;
        As[lc + 2][lr] = av.z; As[lc + 3][lr] = av.w;
        Bs[lc + 0][lr] = bv.x; Bs[lc + 1][lr] = bv.y;
        Bs[lc + 2][lr] = bv.z; Bs[lc + 3][lr] = bv.w;
        __syncthreads();
#pragma unroll
        for (int kk = 0; kk < 8; kk++) {
            float4 a0 = *(const float4*)&As[kk][ty * 8];
            float4 a1 = *(const float4*)&As[kk][ty * 8 + 4];
            u64 b0 = *(const u64*)&Bs[kk][tx * 8 + 0];
            u64 b1 = *(const u64*)&Bs[kk][tx * 8 + 2];
            u64 b2 = *(const u64*)&Bs[kk][tx * 8 + 4];
            u64 b3 = *(const u64*)&Bs[kk][tx * 8 + 6];
            float aa[8] = {a0.x, a0.y, a0.z, a0.w, a1.x, a1.y, a1.z, a1.w};
#pragma unroll
            for (int i = 0; i < 8; i++) {
                u64 a2 = pack2(aa[i], aa[i]);
                fma2(acc[i][0].u, a2, b0);
                fma2(acc[i][1].u, a2, b1);
                fma2(acc[i][2].u, a2, b2);
                fma2(acc[i][3].u, a2, b3);
            }
        }
        __syncthreads();
    }

#pragma unroll
    for (int i = 0; i < 8; i++) {
        float* Cp = C + (size_t)(m0 + ty * 8 + i) * N + n0 + tx * 8;
        float4 c0 = make_float4(acc[i][0].f.x, acc[i][0].f.y,
                                acc[i][1].f.x, acc[i][1].f.y);
        float4 c1 = make_float4(acc[i][2].f.x, acc[i][2].f.y,
                                acc[i][3].f.x, acc[i][3].f.y);
        *(float4*)Cp = c0;
        *(float4*)(Cp + 4) = c1;
    }
}

// ============================================================
// Flash attention: per (b, h, 64-query block).
// 128 threads: ty=tid/8 (16 row-groups of 4 rows), tx=tid%8 (8 col-groups of 8).
// Online softmax with running (m, l). Mask: s = m? 0.125*s : -1.25e8.
// Dynamic smem: Qt[64][68] (e-major), Kt[64][68] (e-major),
//               Vs[64][68] (key-major), Pt[64][68] (key-major).
// ============================================================
#define SM_STRIDE 68
#define SM_TILE   (64 * SM_STRIDE)

__global__ __launch_bounds__(128) void attn_kernel(
    const float* __restrict__ Q, const float* __restrict__ Kg,
    const float* __restrict__ V, const float* __restrict__ mask,
    float* __restrict__ O)
{
    extern __shared__ float smx[];
    float* Qt = smx;                 // Qt[e*68 + i]
    float* Kt = smx + SM_TILE;       // Kt[e*68 + j]
    float* Vs = smx + 2 * SM_TILE;   // Vs[j*68 + e]
    float* Pt = smx + 3 * SM_TILE;   // Pt[j*68 + i]

    const int tid = threadIdx.x;
    const int q0 = blockIdx.x * 64;
    const int h = blockIdx.y;
    const int b = blockIdx.z;
    const int ty = tid >> 3;  // 0..15
    const int tx = tid & 7;   // 0..7

    // Load Q tile transposed into Qt (once)
    {
        int r = tid >> 1;
        int e0 = (tid & 1) * 32;
        const float* src = Q + ((size_t)(b * LL + q0 + r)) * DD + h * DHH + e0;
#pragma unroll
        for (int c = 0; c < 8; c++) {
            float4 v4 = *(const float4*)(src + 4 * c);
            int e = e0 + 4 * c;
            Qt[(e + 0) * SM_STRIDE + r] = v4.x;
            Qt[(e + 1) * SM_STRIDE + r] = v4.y;
            Qt[(e + 2) * SM_STRIDE + r] = v4.z;
            Qt[(e + 3) * SM_STRIDE + r] = v4.w;
        }
    }

    float mrun[4], lrun[4];
    F2 o2[4][4];
#pragma unroll
    for (int i = 0; i < 4; i++) {
        mrun[i] = -INFINITY;
        lrun[i] = 0.f;
#pragma unroll
        for (int j = 0; j < 4; j++) o2[i][j].u = 0ull;
    }

    for (int kb = 0; kb < 16; kb++) {
        const int k0 = kb * 64;
        __syncthreads();  // previous iter's reads of Kt/Vs/Pt done; Qt stores visible
        // Load K (transposed) and V (natural)
        {
            int r = tid >> 1;
            int e0 = (tid & 1) * 32;
            const float* ksrc = Kg + ((size_t)(b * LL + k0 + r)) * DD + h * DHH + e0;
            const float* vsrc = V + ((size_t)(b * LL + k0 + r)) * DD + h * DHH + e0;
#pragma unroll
            for (int c = 0; c < 8; c++) {
                float4 kv = *(const float4*)(ksrc + 4 * c);
                int e = e0 + 4 * c;
                Kt[(e + 0) * SM_STRIDE + r] = kv.x;
                Kt[(e + 1) * SM_STRIDE + r] = kv.y;
                Kt[(e + 2) * SM_STRIDE + r] = kv.z;
                Kt[(e + 3) * SM_STRIDE + r] = kv.w;
                *(float4*)(Vs + r * SM_STRIDE + e) = *(const float4*)(vsrc + 4 * c);
            }
        }
        __syncthreads();

        // S fragment: rows ty*4..+3, cols tx*8..+7
        F2 s2[4][4];
#pragma unroll
        for (int i = 0; i < 4; i++)
#pragma unroll
            for (int j = 0; j < 4; j++) s2[i][j].u = 0ull;

#pragma unroll 16
        for (int e = 0; e < 64; e++) {
            float4 qv = *(const float4*)(Qt + e * SM_STRIDE + ty * 4);
            u64 k20 = *(const u64*)(Kt + e * SM_STRIDE + tx * 8 + 0);
            u64 k21 = *(const u64*)(Kt + e * SM_STRIDE + tx * 8 + 2);
            u64 k22 = *(const u64*)(Kt + e * SM_STRIDE + tx * 8 + 4);
            u64 k23 = *(const u64*)(Kt + e * SM_STRIDE + tx * 8 + 6);
            float qq[4] = {qv.x, qv.y, qv.z, qv.w};
#pragma unroll
            for (int ii = 0; ii < 4; ii++) {
                u64 a2 = pack2(qq[ii], qq[ii]);
                fma2(s2[ii][0].u, a2, k20);
                fma2(s2[ii][1].u, a2, k21);
                fma2(s2[ii][2].u, a2, k22);
                fma2(s2[ii][3].u, a2, k23);
            }
        }

        // Online softmax per owned row (replicated across the 8 tx threads)
#pragma unroll
        for (int ii = 0; ii < 4; ii++) {
            float sv[8];
            sv[0] = s2[ii][0].f.x; sv[1] = s2[ii][0].f.y;
            sv[2] = s2[ii][1].f.x; sv[3] = s2[ii][1].f.y;
            sv[4] = s2[ii][2].f.x; sv[5] = s2[ii][2].f.y;
            sv[6] = s2[ii][3].f.x; sv[7] = s2[ii][3].f.y;

            const float* mp = mask + (size_t)(q0 + ty * 4 + ii) * LL + k0 + tx * 8;
            float4 m4a = *(const float4*)mp;
            float4 m4b = *(const float4*)(mp + 4);
            float mm[8] = {m4a.x, m4a.y, m4a.z, m4a.w, m4b.x, m4b.y, m4b.z, m4b.w};
#pragma unroll
            for (int e = 0; e < 8; e++)
                sv[e] = (mm[e] != 0.f) ? sv[e] * 0.125f : -1.25e8f;

            float rmax = sv[0];
#pragma unroll
            for (int e = 1; e < 8; e++) rmax = fmaxf(rmax, sv[e]);
            rmax = fmaxf(rmax, __shfl_xor_sync(0xffffffffu, rmax, 1));
            rmax = fmaxf(rmax, __shfl_xor_sync(0xffffffffu, rmax, 2));
            rmax = fmaxf(rmax, __shfl_xor_sync(0xffffffffu, rmax, 4));

            float nm = fmaxf(mrun[ii], rmax);
            float corr = __expf(mrun[ii] - nm);
            mrun[ii] = nm;

            float rsum = 0.f;
#pragma unroll
            for (int e = 0; e < 8; e++) {
                float p = __expf(sv[e] - nm);
                sv[e] = p;
                rsum += p;
            }
            rsum += __shfl_xor_sync(0xffffffffu, rsum, 1);
            rsum += __shfl_xor_sync(0xffffffffu, rsum, 2);
            rsum += __shfl_xor_sync(0xffffffffu, rsum, 4);
            lrun[ii] = lrun[ii] * corr + rsum;

            u64 c2 = pack2(corr, corr);
#pragma unroll
            for (int j = 0; j < 4; j++) mul2(o2[ii][j].u, c2);

#pragma unroll
            for (int e = 0; e < 8; e++)
                Pt[(tx * 8 + e) * SM_STRIDE + ty * 4 + ii] = sv[e];
        }
        __syncthreads();

        // O += P @ V : rows ty*4..+3, dh cols tx*8..+7
#pragma unroll 16
        for (int j = 0; j < 64; j++) {
            float4 pv = *(const float4*)(Pt + j * SM_STRIDE + ty * 4);
            u64 v20 = *(const u64*)(Vs + j * SM_STRIDE + tx * 8 + 0);
            u64 v21 = *(const u64*)(Vs + j * SM_STRIDE + tx * 8 + 2);
            u64 v22 = *(const u64*)(Vs + j * SM_STRIDE + tx * 8 + 4);
            u64 v23 = *(const u64*)(Vs + j * SM_STRIDE + tx * 8 + 6);
            float pp[4] = {pv.x, pv.y, pv.z, pv.w};
#pragma unroll
            for (int ii = 0; ii < 4; ii++) {
                u64 a2 = pack2(pp[ii], pp[ii]);
                fma2(o2[ii][0].u, a2, v20);
                fma2(o2[ii][1].u, a2, v21);
                fma2(o2[ii][2].u, a2, v22);
                fma2(o2[ii][3].u, a2, v23);
            }
        }
    }

    // Epilogue: normalize and store to (B, L, D) layout
#pragma unroll
    for (int ii = 0; ii < 4; ii++) {
        float inv = 1.f / lrun[ii];
        float* dst = O + ((size_t)(b * LL + q0 + ty * 4 + ii)) * DD + h * DHH + tx * 8;
        float4 c0 = make_float4(o2[ii][0].f.x * inv, o2[ii][0].f.y * inv,
                                o2[ii][1].f.x * inv, o2[ii][1].f.y * inv);
        float4 c1 = make_float4(o2[ii][2].f.x * inv, o2[ii][2].f.y * inv,
                                o2[ii][3].f.x * inv, o2[ii][3].f.y * inv);
        *(float4*)dst = c0;
        *(float4*)(dst + 4) = c1;
    }
}

// ============================================================
// Launch
// ============================================================
extern "C" void kernel_launch(void* const* d_in, const int* in_sizes, int n_in,
                              void* d_out, int out_size)
{
    const float* x    = (const float*)d_in[0];
    const float* mask = (const float*)d_in[1];
    const float* Wk   = (const float*)d_in[2];
    const float* Wv   = (const float*)d_in[3];
    const float* Wq   = (const float*)d_in[4];
    const float* Wo   = (const float*)d_in[5];
    float* out = (float*)d_out;

    float *gq, *gk, *gv, *ga;
    cudaGetSymbolAddress((void**)&gq, g_q);
    cudaGetSymbolAddress((void**)&gk, g_k);
    cudaGetSymbolAddress((void**)&gv, g_v);
    cudaGetSymbolAddress((void**)&ga, g_a);

    const int M = BB * LL;  // 8192
    dim3 ggrid(1024 / 128, M / 128);  // (8, 64)
    dim3 gblk(256);

    gemm_nt_kernel<<<ggrid, gblk>>>(x, Wq, gq, M);
    gemm_nt_kernel<<<ggrid, gblk>>>(x, Wk, gk, M);
    gemm_nt_kernel<<<ggrid, gblk>>>(x, Wv, gv, M);

    static int smem_set = 0;
    const int attn_smem = 4 * SM_TILE * (int)sizeof(float);  // 69632
    if (!smem_set) {
        cudaFuncSetAttribute(attn_kernel,
                             cudaFuncAttributeMaxDynamicSharedMemorySize,
                             attn_smem);
        smem_set = 1;
    }
    dim3 agrid(LL / 64, HH, BB);  // (16, 16, 8)
    attn_kernel<<<agrid, 128, attn_smem>>>(gq, gk, gv, mask, ga);

    gemm_nt_kernel<<<ggrid, gblk>>>(ga, Wo, out, M);
}

// round 3
// speedup vs baseline: 1.5245x; 1.5245x over previous
#include <cuda_runtime.h>
#include <cuda_bf16.h>
#include <math.h>
#include <stdint.h>

// Problem constants
#define BB  8
#define LL  1024
#define DD  1024
#define HH  16
#define DHH 64
#define MM  (BB * LL)   // 8192

typedef unsigned long long u64;
union F2 { u64 u; float2 f; };

// ---------------- device-global scratch (no allocs allowed) ----------------
__device__ float g_q[MM * DD];
__device__ float g_k[MM * DD];
__device__ float g_v[MM * DD];
__device__ float g_a[MM * DD];
__device__ __nv_bfloat16 g_xh[MM * DD], g_xl[MM * DD];
__device__ __nv_bfloat16 g_ah[MM * DD], g_al[MM * DD];
__device__ __nv_bfloat16 g_wh[4][DD * DD], g_wl[4][DD * DD];

// ---------------- PTX helpers (plain sm_103-safe ISA only) ----------------
__device__ __forceinline__ uint32_t s2u(const void* p) {
    uint32_t a;
    asm("{ .reg .u64 t; cvta.to.shared.u64 t, %1; cvt.u32.u64 %0, t; }"
        : "=r"(a) : "l"(p));
    return a;
}
__device__ __forceinline__ void cp16(uint32_t d, const void* s) {
    asm volatile("cp.async.cg.shared.global [%0], [%1], 16;" :: "r"(d), "l"(s));
}
__device__ __forceinline__ void cp_commit() {
    asm volatile("cp.async.commit_group;");
}
template <int N> __device__ __forceinline__ void cp_wait() {
    asm volatile("cp.async.wait_group %0;" :: "n"(N));
}
__device__ __forceinline__ void ldm4(uint32_t& r0, uint32_t& r1,
                                     uint32_t& r2, uint32_t& r3, uint32_t a) {
    asm volatile("ldmatrix.sync.aligned.m8n8.x4.shared.b16 {%0,%1,%2,%3}, [%4];"
                 : "=r"(r0), "=r"(r1), "=r"(r2), "=r"(r3) : "r"(a));
}
__device__ __forceinline__ void mma16816(float* c, uint32_t a0, uint32_t a1,
                                         uint32_t a2, uint32_t a3,
                                         uint32_t b0, uint32_t b1) {
    asm volatile(
        "mma.sync.aligned.m16n8k16.row.col.f32.bf16.bf16.f32 "
        "{%0,%1,%2,%3}, {%4,%5,%6,%7}, {%8,%9}, {%0,%1,%2,%3};"
        : "+f"(c[0]), "+f"(c[1]), "+f"(c[2]), "+f"(c[3])
        : "r"(a0), "r"(a1), "r"(a2), "r"(a3), "r"(b0), "r"(b1));
}

// ---------------- packed f32x2 helpers (attention kernel) ----------------
__device__ __forceinline__ u64 pack2(float x, float y) {
    u64 r;
    asm("mov.b64 %0, {%1, %2};" : "=l"(r) : "f"(x), "f"(y));
    return r;
}
__device__ __forceinline__ void fma2(u64& d, u64 a, u64 b) {
    asm("fma.rn.f32x2 %0, %1, %2, %3;" : "=l"(d) : "l"(a), "l"(b), "l"(d));
}
__device__ __forceinline__ void mul2(u64& d, u64 a) {
    asm("mul.rn.f32x2 %0, %1, %2;" : "=l"(d) : "l"(d), "l"(a));
}

// ============================================================
// split: fp32 -> (bf16 hi, bf16 lo of residual)
// ============================================================
__global__ __launch_bounds__(256) void split_kernel(
    const float4* __restrict__ src,
    __nv_bfloat162* __restrict__ hi, __nv_bfloat162* __restrict__ lo, int n4)
{
    int i = blockIdx.x * blockDim.x + threadIdx.x;
    if (i >= n4) return;
    float4 v = src[i];
    __nv_bfloat16 hx = __float2bfloat16(v.x);
    __nv_bfloat16 hy = __float2bfloat16(v.y);
    __nv_bfloat16 hz = __float2bfloat16(v.z);
    __nv_bfloat16 hw = __float2bfloat16(v.w);
    float rx = v.x - __bfloat162float(hx);
    float ry = v.y - __bfloat162float(hy);
    float rz = v.z - __bfloat162float(hz);
    float rw = v.w - __bfloat162float(hw);
    hi[2 * i + 0] = __nv_bfloat162(hx, hy);
    hi[2 * i + 1] = __nv_bfloat162(hz, hw);
    lo[2 * i + 0] = __floats2bfloat162_rn(rx, ry);
    lo[2 * i + 1] = __floats2bfloat162_rn(rz, rw);
}

// ============================================================
// mma.sync bf16-split GEMM (NT): C[M,1024] = A[M,1024] * B[1024,1024]^T
//   C = Ah*Bh^T + Ah*Bl^T + Al*Bh^T   (fp32 accumulate)
// CTA 128x128x32, 8 warps (2m x 4n), warp tile 64x32.
// Double-buffered cp.async. Rows of 32 bf16 (64B), XOR-swizzled 16B chunks.
// ============================================================
#define BK 32
#define NKI (DD / BK)          // 32 k-iterations
#define MAT_B 8192             // 128 rows * 64 bytes
#define STG_B (4 * MAT_B)      // Ah, Al, Bh, Bl
#define OFF_AH 0
#define OFF_AL MAT_B
#define OFF_BH (2 * MAT_B)
#define OFF_BL (3 * MAT_B)
#define GSMEM (2 * STG_B)      // 65536

// swizzled in-tile byte offset for (row, 16B-chunk c)
__device__ __forceinline__ uint32_t swz(int row, int c) {
    return (uint32_t)(row * 64 + ((c ^ (row & 3)) << 4));
}

__device__ __forceinline__ void g_load_stage(
    uint32_t sbase,
    const __nv_bfloat16* __restrict__ Ah, const __nv_bfloat16* __restrict__ Al,
    const __nv_bfloat16* __restrict__ Bh, const __nv_bfloat16* __restrict__ Bl,
    int m0, int n0, int k0, int tid)
{
    const int r1 = tid >> 2;          // 0..63
    const int r2 = r1 + 64;           // 64..127
    const int c = tid & 3;            // 16B chunk
    const int kc = k0 + c * 8;
    const size_t a1 = (size_t)(m0 + r1) * DD + kc;
    const size_t a2 = (size_t)(m0 + r2) * DD + kc;
    const size_t b1 = (size_t)(n0 + r1) * DD + kc;
    const size_t b2 = (size_t)(n0 + r2) * DD + kc;
    const uint32_t s1 = swz(r1, c), s2 = swz(r2, c);
    cp16(sbase + OFF_AH + s1, Ah + a1);
    cp16(sbase + OFF_AH + s2, Ah + a2);
    cp16(sbase + OFF_AL + s1, Al + a1);
    cp16(sbase + OFF_AL + s2, Al + a2);
    cp16(sbase + OFF_BH + s1, Bh + b1);
    cp16(sbase + OFF_BH + s2, Bh + b2);
    cp16(sbase + OFF_BL + s1, Bl + b1);
    cp16(sbase + OFF_BL + s2, Bl + b2);
}

__global__ __launch_bounds__(256, 1) void gemm_mma_kernel(
    const __nv_bfloat16* __restrict__ Ah, const __nv_bfloat16* __restrict__ Al,
    const __nv_bfloat16* __restrict__ Bh, const __nv_bfloat16* __restrict__ Bl,
    float* __restrict__ C)
{
    extern __shared__ char smg[];
    const uint32_t sbase = s2u(smg);

    const int tid = threadIdx.x;
    const int wid = tid >> 5;
    const int lane = tid & 31;
    const int m0 = blockIdx.y * 128;
    const int n0 = blockIdx.x * 128;
    const int wm0 = (wid & 1) * 64;   // warp m offset in tile
    const int wn0 = (wid >> 1) * 32;  // warp n offset in tile

    float acc[4][4][4];
#pragma unroll
    for (int i = 0; i < 4; i++)
#pragma unroll
        for (int j = 0; j < 4; j++)
#pragma unroll
            for (int r = 0; r < 4; r++) acc[i][j][r] = 0.f;

    // lane-invariant parts of ldmatrix addressing
    const int a_row_l = ((lane >> 3) & 1) * 8 + (lane & 7);  // + mt*16 + wm0
    const int a_cl = lane >> 4;                              // + kk*2
    const int b_row_l = (lane >> 4) * 8 + (lane & 7);        // + ng*16 + wn0
    const int b_cl = (lane >> 3) & 1;                        // + kk*2

    g_load_stage(sbase + 0 * STG_B, Ah, Al, Bh, Bl, m0, n0, 0, tid);
    cp_commit();
    g_load_stage(sbase + 1 * STG_B, Ah, Al, Bh, Bl, m0, n0, BK, tid);
    cp_commit();

    for (int k = 0; k < NKI; k++) {
        cp_wait<1>();
        __syncthreads();
        const uint32_t st = sbase + (k & 1) * STG_B;

#pragma unroll
        for (int kk = 0; kk < 2; kk++) {
            uint32_t ah[4][4], al[4][4], bh[2][4], bl[2][4];
#pragma unroll
            for (int mt = 0; mt < 4; mt++) {
                int row = wm0 + mt * 16 + a_row_l;
                int c = kk * 2 + a_cl;
                uint32_t off = swz(row, c);
                ldm4(ah[mt][0], ah[mt][1], ah[mt][2], ah[mt][3],
                     st + OFF_AH + off);
                ldm4(al[mt][0], al[mt][1], al[mt][2], al[mt][3],
                     st + OFF_AL + off);
            }
#pragma unroll
            for (int ng = 0; ng < 2; ng++) {
                int row = wn0 + ng * 16 + b_row_l;
                int c = kk * 2 + b_cl;
                uint32_t off = swz(row, c);
                ldm4(bh[ng][0], bh[ng][1], bh[ng][2], bh[ng][3],
                     st + OFF_BH + off);
                ldm4(bl[ng][0], bl[ng][1], bl[ng][2], bl[ng][3],
                     st + OFF_BL + off);
            }
#pragma unroll
            for (int mt = 0; mt < 4; mt++) {
#pragma unroll
                for (int nt = 0; nt < 4; nt++) {
                    const int ng = nt >> 1, hb = (nt & 1) * 2;
                    mma16816(acc[mt][nt], ah[mt][0], ah[mt][1], ah[mt][2],
                             ah[mt][3], bh[ng][hb], bh[ng][hb + 1]);
                    mma16816(acc[mt][nt], ah[mt][0], ah[mt][1], ah[mt][2],
                             ah[mt][3], bl[ng][hb], bl[ng][hb + 1]);
                    mma16816(acc[mt][nt], al[mt][0], al[mt][1], al[mt][2],
                             al[mt][3], bh[ng][hb], bh[ng][hb + 1]);
                }
            }
        }
        __syncthreads();
        if (k + 2 < NKI)
            g_load_stage(sbase + (k & 1) * STG_B, Ah, Al, Bh, Bl,
                         m0, n0, (k + 2) * BK, tid);
        cp_commit();
    }

    // epilogue
    const int er = lane >> 2;
    const int ec = (lane & 3) * 2;
#pragma unroll
    for (int mt = 0; mt < 4; mt++) {
#pragma unroll
        for (int nt = 0; nt < 4; nt++) {
            float* p0 = C + (size_t)(m0 + wm0 + mt * 16 + er) * DD
                          + n0 + wn0 + nt * 8 + ec;
            float* p1 = p0 + 8 * DD;
            *(float2*)p0 = make_float2(acc[mt][nt][0], acc[mt][nt][1]);
            *(float2*)p1 = make_float2(acc[mt][nt][2], acc[mt][nt][3]);
        }
    }
}

// ============================================================
// Flash attention (fp32, f32x2 FFMA) — unchanged
// ============================================================
#define SM_STRIDE 68
#define SM_TILE   (64 * SM_STRIDE)

__global__ __launch_bounds__(128) void attn_kernel(
    const float* __restrict__ Q, const float* __restrict__ Kg,
    const float* __restrict__ V, const float* __restrict__ mask,
    float* __restrict__ O)
{
    extern __shared__ float smx[];
    float* Qt = smx;
    float* Kt = smx + SM_TILE;
    float* Vs = smx + 2 * SM_TILE;
    float* Pt = smx + 3 * SM_TILE;

    const int tid = threadIdx.x;
    const int q0 = blockIdx.x * 64;
    const int h = blockIdx.y;
    const int b = blockIdx.z;
    const int ty = tid >> 3;
    const int tx = tid & 7;

    {
        int r = tid >> 1;
        int e0 = (tid & 1) * 32;
        const float* src = Q + ((size_t)(b * LL + q0 + r)) * DD + h * DHH + e0;
#pragma unroll
        for (int c = 0; c < 8; c++) {
            float4 v4 = *(const float4*)(src + 4 * c);
            int e = e0 + 4 * c;
            Qt[(e + 0) * SM_STRIDE + r] = v4.x;
            Qt[(e + 1) * SM_STRIDE + r] = v4.y;
            Qt[(e + 2) * SM_STRIDE + r] = v4.z;
            Qt[(e + 3) * SM_STRIDE + r] = v4.w;
        }
    }

    float mrun[4], lrun[4];
    F2 o2[4][4];
#pragma unroll
    for (int i = 0; i < 4; i++) {
        mrun[i] = -INFINITY;
        lrun[i] = 0.f;
#pragma unroll
        for (int j = 0; j < 4; j++) o2[i][j].u = 0ull;
    }

    for (int kb = 0; kb < 16; kb++) {
        const int k0 = kb * 64;
        __syncthreads();
        {
            int r = tid >> 1;
            int e0 = (tid & 1) * 32;
            const float* ksrc = Kg + ((size_t)(b * LL + k0 + r)) * DD + h * DHH + e0;
            const float* vsrc = V + ((size_t)(b * LL + k0 + r)) * DD + h * DHH + e0;
#pragma unroll
            for (int c = 0; c < 8; c++) {
                float4 kv = *(const float4*)(ksrc + 4 * c);
                int e = e0 + 4 * c;
                Kt[(e + 0) * SM_STRIDE + r] = kv.x;
                Kt[(e + 1) * SM_STRIDE + r] = kv.y;
                Kt[(e + 2) * SM_STRIDE + r] = kv.z;
                Kt[(e + 3) * SM_STRIDE + r] = kv.w;
                *(float4*)(Vs + r * SM_STRIDE + e) = *(const float4*)(vsrc + 4 * c);
            }
        }
        __syncthreads();

        F2 s2[4][4];
#pragma unroll
        for (int i = 0; i < 4; i++)
#pragma unroll
            for (int j = 0; j < 4; j++) s2[i][j].u = 0ull;

#pragma unroll 16
        for (int e = 0; e < 64; e++) {
            float4 qv = *(const float4*)(Qt + e * SM_STRIDE + ty * 4);
            u64 k20 = *(const u64*)(Kt + e * SM_STRIDE + tx * 8 + 0);
            u64 k21 = *(const u64*)(Kt + e * SM_STRIDE + tx * 8 + 2);
            u64 k22 = *(const u64*)(Kt + e * SM_STRIDE + tx * 8 + 4);
            u64 k23 = *(const u64*)(Kt + e * SM_STRIDE + tx * 8 + 6);
            float qq[4] = {qv.x, qv.y, qv.z, qv.w};
#pragma unroll
            for (int ii = 0; ii < 4; ii++) {
                u64 a2 = pack2(qq[ii], qq[ii]);
                fma2(s2[ii][0].u, a2, k20);
                fma2(s2[ii][1].u, a2, k21);
                fma2(s2[ii][2].u, a2, k22);
                fma2(s2[ii][3].u, a2, k23);
            }
        }

#pragma unroll
        for (int ii = 0; ii < 4; ii++) {
            float sv[8];
            sv[0] = s2[ii][0].f.x; sv[1] = s2[ii][0].f.y;
            sv[2] = s2[ii][1].f.x; sv[3] = s2[ii][1].f.y;
            sv[4] = s2[ii][2].f.x; sv[5] = s2[ii][2].f.y;
            sv[6] = s2[ii][3].f.x; sv[7] = s2[ii][3].f.y;

            const float* mp = mask + (size_t)(q0 + ty * 4 + ii) * LL + k0 + tx * 8;
            float4 m4a = *(const float4*)mp;
            float4 m4b = *(const float4*)(mp + 4);
            float mm[8] = {m4a.x, m4a.y, m4a.z, m4a.w, m4b.x, m4b.y, m4b.z, m4b.w};
#pragma unroll
            for (int e = 0; e < 8; e++)
                sv[e] = (mm[e] != 0.f) ? sv[e] * 0.125f : -1.25e8f;

            float rmax = sv[0];
#pragma unroll
            for (int e = 1; e < 8; e++) rmax = fmaxf(rmax, sv[e]);
            rmax = fmaxf(rmax, __shfl_xor_sync(0xffffffffu, rmax, 1));
            rmax = fmaxf(rmax, __shfl_xor_sync(0xffffffffu, rmax, 2));
            rmax = fmaxf(rmax, __shfl_xor_sync(0xffffffffu, rmax, 4));

            float nm = fmaxf(mrun[ii], rmax);
            float corr = __expf(mrun[ii] - nm);
            mrun[ii] = nm;

            float rsum = 0.f;
#pragma unroll
            for (int e = 0; e < 8; e++) {
                float p = __expf(sv[e] - nm);
                sv[e] = p;
                rsum += p;
            }
            rsum += __shfl_xor_sync(0xffffffffu, rsum, 1);
            rsum += __shfl_xor_sync(0xffffffffu, rsum, 2);
            rsum += __shfl_xor_sync(0xffffffffu, rsum, 4);
            lrun[ii] = lrun[ii] * corr + rsum;

            u64 c2 = pack2(corr, corr);
#pragma unroll
            for (int j = 0; j < 4; j++) mul2(o2[ii][j].u, c2);

#pragma unroll
            for (int e = 0; e < 8; e++)
                Pt[(tx * 8 + e) * SM_STRIDE + ty * 4 + ii] = sv[e];
        }
        __syncthreads();

#pragma unroll 16
        for (int j = 0; j < 64; j++) {
            float4 pv = *(const float4*)(Pt + j * SM_STRIDE + ty * 4);
            u64 v20 = *(const u64*)(Vs + j * SM_STRIDE + tx * 8 + 0);
            u64 v21 = *(const u64*)(Vs + j * SM_STRIDE + tx * 8 + 2);
            u64 v22 = *(const u64*)(Vs + j * SM_STRIDE + tx * 8 + 4);
            u64 v23 = *(const u64*)(Vs + j * SM_STRIDE + tx * 8 + 6);
            float pp[4] = {pv.x, pv.y, pv.z, pv.w};
#pragma unroll
            for (int ii = 0; ii < 4; ii++) {
                u64 a2 = pack2(pp[ii], pp[ii]);
                fma2(o2[ii][0].u, a2, v20);
                fma2(o2[ii][1].u, a2, v21);
                fma2(o2[ii][2].u, a2, v22);
                fma2(o2[ii][3].u, a2, v23);
            }
        }
    }

#pragma unroll
    for (int ii = 0; ii < 4; ii++) {
        float inv = 1.f / lrun[ii];
        float* dst = O + ((size_t)(b * LL + q0 + ty * 4 + ii)) * DD + h * DHH + tx * 8;
        float4 c0 = make_float4(o2[ii][0].f.x * inv, o2[ii][0].f.y * inv,
                                o2[ii][1].f.x * inv, o2[ii][1].f.y * inv);
        float4 c1 = make_float4(o2[ii][2].f.x * inv, o2[ii][2].f.y * inv,
                                o2[ii][3].f.x * inv, o2[ii][3].f.y * inv);
        *(float4*)dst = c0;
        *(float4*)(dst + 4) = c1;
    }
}

// ============================================================
// Launch
// ============================================================
extern "C" void kernel_launch(void* const* d_in, const int* in_sizes, int n_in,
                              void* d_out, int out_size)
{
    const float* x    = (const float*)d_in[0];
    const float* mask = (const float*)d_in[1];
    const float* Wk   = (const float*)d_in[2];
    const float* Wv   = (const float*)d_in[3];
    const float* Wq   = (const float*)d_in[4];
    const float* Wo   = (const float*)d_in[5];
    float* out = (float*)d_out;

    float *gq, *gk, *gv, *ga;
    __nv_bfloat16 *xh, *xl, *ah, *al, *wh, *wl;
    cudaGetSymbolAddress((void**)&gq, g_q);
    cudaGetSymbolAddress((void**)&gk, g_k);
    cudaGetSymbolAddress((void**)&gv, g_v);
    cudaGetSymbolAddress((void**)&ga, g_a);
    cudaGetSymbolAddress((void**)&xh, g_xh);
    cudaGetSymbolAddress((void**)&xl, g_xl);
    cudaGetSymbolAddress((void**)&ah, g_ah);
    cudaGetSymbolAddress((void**)&al, g_al);
    cudaGetSymbolAddress((void**)&wh, g_wh);
    cudaGetSymbolAddress((void**)&wl, g_wl);

    static int attr_set = 0;
    const int attn_smem = 4 * SM_TILE * (int)sizeof(float);
    if (!attr_set) {
        cudaFuncSetAttribute(attn_kernel,
                             cudaFuncAttributeMaxDynamicSharedMemorySize, attn_smem);
        cudaFuncSetAttribute(gemm_mma_kernel,
                             cudaFuncAttributeMaxDynamicSharedMemorySize, GSMEM);
        attr_set = 1;
    }

    // 1) splits: x and the 4 weights (order: Wk, Wv, Wq, Wo)
    {
        int n4 = MM * DD / 4;
        split_kernel<<<(n4 + 255) / 256, 256>>>(
            (const float4*)x, (__nv_bfloat162*)xh, (__nv_bfloat162*)xl, n4);
        int w4 = DD * DD / 4;
        const float* ws[4] = {Wk, Wv, Wq, Wo};
        for (int i = 0; i < 4; i++) {
            split_kernel<<<(w4 + 255) / 256, 256>>>(
                (const float4*)ws[i],
                (__nv_bfloat162*)(wh + (size_t)i * DD * DD),
                (__nv_bfloat162*)(wl + (size_t)i * DD * DD), w4);
        }
    }

    // 2) projection GEMMs on tensor cores (mma.sync)
    dim3 ggrid(DD / 128, MM / 128);  // (8, 64)
    gemm_mma_kernel<<<ggrid, 256, GSMEM>>>(xh, xl,
        wh + (size_t)2 * DD * DD, wl + (size_t)2 * DD * DD, gq);  // Wq
    gemm_mma_kernel<<<ggrid, 256, GSMEM>>>(xh, xl,
        wh + (size_t)0 * DD * DD, wl + (size_t)0 * DD * DD, gk);  // Wk
    gemm_mma_kernel<<<ggrid, 256, GSMEM>>>(xh, xl,
        wh + (size_t)1 * DD * DD, wl + (size_t)1 * DD * DD, gv);  // Wv

    // 3) attention
    dim3 agrid(LL / 64, HH, BB);
    attn_kernel<<<agrid, 128, attn_smem>>>(gq, gk, gv, mask, ga);

    // 4) output projection
    {
        int n4 = MM * DD / 4;
        split_kernel<<<(n4 + 255) / 256, 256>>>(
            (const float4*)ga, (__nv_bfloat162*)ah, (__nv_bfloat162*)al, n4);
    }
    gemm_mma_kernel<<<ggrid, 256, GSMEM>>>(ah, al,
        wh + (size_t)3 * DD * DD, wl + (size_t)3 * DD * DD, out);  // Wo
}

// round 4
// speedup vs baseline: 1.5260x; 1.0010x over previous
#include <cuda_runtime.h>
#include <cuda_bf16.h>
#include <math.h>
#include <stdint.h>

// Problem constants
#define BB  8
#define LL  1024
#define DD  1024
#define HH  16
#define DHH 64
#define MM  (BB * LL)   // 8192

typedef unsigned long long u64;
union F2 { u64 u; float2 f; };

// ---------------- device-global scratch (no allocs allowed) ----------------
__device__ float g_q[MM * DD];
__device__ float g_k[MM * DD];
__device__ float g_v[MM * DD];
__device__ float g_a[MM * DD];
__device__ __nv_bfloat16 g_xh[MM * DD], g_xl[MM * DD];
__device__ __nv_bfloat16 g_ah[MM * DD], g_al[MM * DD];
__device__ __nv_bfloat16 g_wh[4][DD * DD], g_wl[4][DD * DD];

// ---------------- PTX helpers (plain sm_103-safe ISA only) ----------------
__device__ __forceinline__ uint32_t s2u(const void* p) {
    uint32_t a;
    asm("{ .reg .u64 t; cvta.to.shared.u64 t, %1; cvt.u32.u64 %0, t; }"
        : "=r"(a) : "l"(p));
    return a;
}
__device__ __forceinline__ void cp16(uint32_t d, const void* s) {
    asm volatile("cp.async.cg.shared.global [%0], [%1], 16;" :: "r"(d), "l"(s));
}
__device__ __forceinline__ void cp_commit() {
    asm volatile("cp.async.commit_group;");
}
template <int N> __device__ __forceinline__ void cp_wait() {
    asm volatile("cp.async.wait_group %0;" :: "n"(N));
}
__device__ __forceinline__ void ldm4(uint32_t& r0, uint32_t& r1,
                                     uint32_t& r2, uint32_t& r3, uint32_t a) {
    asm volatile("ldmatrix.sync.aligned.m8n8.x4.shared.b16 {%0,%1,%2,%3}, [%4];"
                 : "=r"(r0), "=r"(r1), "=r"(r2), "=r"(r3) : "r"(a));
}
__device__ __forceinline__ void mma16816(float* c, uint32_t a0, uint32_t a1,
                                         uint32_t a2, uint32_t a3,
                                         uint32_t b0, uint32_t b1) {
    asm volatile(
        "mma.sync.aligned.m16n8k16.row.col.f32.bf16.bf16.f32 "
        "{%0,%1,%2,%3}, {%4,%5,%6,%7}, {%8,%9}, {%0,%1,%2,%3};"
        : "+f"(c[0]), "+f"(c[1]), "+f"(c[2]), "+f"(c[3])
        : "r"(a0), "r"(a1), "r"(a2), "r"(a3), "r"(b0), "r"(b1));
}

// ---------------- packed f32x2 helpers (attention kernel) ----------------
__device__ __forceinline__ u64 pack2(float x, float y) {
    u64 r;
    asm("mov.b64 %0, {%1, %2};" : "=l"(r) : "f"(x), "f"(y));
    return r;
}
__device__ __forceinline__ void fma2(u64& d, u64 a, u64 b) {
    asm("fma.rn.f32x2 %0, %1, %2, %3;" : "=l"(d) : "l"(a), "l"(b), "l"(d));
}
__device__ __forceinline__ void mul2(u64& d, u64 a) {
    asm("mul.rn.f32x2 %0, %1, %2;" : "=l"(d) : "l"(d), "l"(a));
}

// ============================================================
// split: fp32 -> (bf16 hi, bf16 lo of residual)
// ============================================================
__global__ __launch_bounds__(256) void split_kernel(
    const float4* __restrict__ src,
    __nv_bfloat162* __restrict__ hi, __nv_bfloat162* __restrict__ lo, int n4)
{
    int i = blockIdx.x * blockDim.x + threadIdx.x;
    if (i >= n4) return;
    float4 v = src[i];
    __nv_bfloat16 hx = __float2bfloat16(v.x);
    __nv_bfloat16 hy = __float2bfloat16(v.y);
    __nv_bfloat16 hz = __float2bfloat16(v.z);
    __nv_bfloat16 hw = __float2bfloat16(v.w);
    float rx = v.x - __bfloat162float(hx);
    float ry = v.y - __bfloat162float(hy);
    float rz = v.z - __bfloat162float(hz);
    float rw = v.w - __bfloat162float(hw);
    hi[2 * i + 0] = __nv_bfloat162(hx, hy);
    hi[2 * i + 1] = __nv_bfloat162(hz, hw);
    lo[2 * i + 0] = __floats2bfloat162_rn(rx, ry);
    lo[2 * i + 1] = __floats2bfloat162_rn(rz, rw);
}

// ============================================================
// mma.sync bf16-split GEMM (NT): C[M,1024] = A[M,1024] * B[1024,1024]^T
//   C = Ah*Bh^T + Ah*Bl^T + Al*Bh^T   (fp32 accumulate)
// CTA 128x128x32, 8 warps (2m x 4n), warp tile 64x32.
// Double-buffered cp.async. Rows of 32 bf16 (64B), XOR-swizzled 16B chunks.
// ============================================================
#define BK 32
#define NKI (DD / BK)          // 32 k-iterations
#define MAT_B 8192             // 128 rows * 64 bytes
#define STG_B (4 * MAT_B)      // Ah, Al, Bh, Bl
#define OFF_AH 0
#define OFF_AL MAT_B
#define OFF_BH (2 * MAT_B)
#define OFF_BL (3 * MAT_B)
#define GSMEM (2 * STG_B)      // 65536

// swizzled in-tile byte offset for (row, 16B-chunk c)
__device__ __forceinline__ uint32_t swz(int row, int c) {
    return (uint32_t)(row * 64 + ((c ^ (row & 3)) << 4));
}

__device__ __forceinline__ void g_load_stage(
    uint32_t sbase,
    const __nv_bfloat16* __restrict__ Ah, const __nv_bfloat16* __restrict__ Al,
    const __nv_bfloat16* __restrict__ Bh, const __nv_bfloat16* __restrict__ Bl,
    int m0, int n0, int k0, int tid)
{
    const int r1 = tid >> 2;          // 0..63
    const int r2 = r1 + 64;           // 64..127
    const int c = tid & 3;            // 16B chunk
    const int kc = k0 + c * 8;
    const size_t a1 = (size_t)(m0 + r1) * DD + kc;
    const size_t a2 = (size_t)(m0 + r2) * DD + kc;
    const size_t b1 = (size_t)(n0 + r1) * DD + kc;
    const size_t b2 = (size_t)(n0 + r2) * DD + kc;
    const uint32_t s1 = swz(r1, c), s2 = swz(r2, c);
    cp16(sbase + OFF_AH + s1, Ah + a1);
    cp16(sbase + OFF_AH + s2, Ah + a2);
    cp16(sbase + OFF_AL + s1, Al + a1);
    cp16(sbase + OFF_AL + s2, Al + a2);
    cp16(sbase + OFF_BH + s1, Bh + b1);
    cp16(sbase + OFF_BH + s2, Bh + b2);
    cp16(sbase + OFF_BL + s1, Bl + b1);
    cp16(sbase + OFF_BL + s2, Bl + b2);
}

__global__ __launch_bounds__(256, 1) void gemm_mma_kernel(
    const __nv_bfloat16* __restrict__ Ah, const __nv_bfloat16* __restrict__ Al,
    const __nv_bfloat16* __restrict__ Bh, const __nv_bfloat16* __restrict__ Bl,
    float* __restrict__ C)
{
    extern __shared__ char smg[];
    const uint32_t sbase = s2u(smg);

    const int tid = threadIdx.x;
    const int wid = tid >> 5;
    const int lane = tid & 31;
    const int m0 = blockIdx.y * 128;
    const int n0 = blockIdx.x * 128;
    const int wm0 = (wid & 1) * 64;   // warp m offset in tile
    const int wn0 = (wid >> 1) * 32;  // warp n offset in tile

    float acc[4][4][4];
#pragma unroll
    for (int i = 0; i < 4; i++)
#pragma unroll
        for (int j = 0; j < 4; j++)
#pragma unroll
            for (int r = 0; r < 4; r++) acc[i][j][r] = 0.f;

    // lane-invariant parts of ldmatrix addressing
    const int a_row_l = ((lane >> 3) & 1) * 8 + (lane & 7);  // + mt*16 + wm0
    const int a_cl = lane >> 4;                              // + kk*2
    const int b_row_l = (lane >> 4) * 8 + (lane & 7);        // + ng*16 + wn0
    const int b_cl = (lane >> 3) & 1;                        // + kk*2

    g_load_stage(sbase + 0 * STG_B, Ah, Al, Bh, Bl, m0, n0, 0, tid);
    cp_commit();
    g_load_stage(sbase + 1 * STG_B, Ah, Al, Bh, Bl, m0, n0, BK, tid);
    cp_commit();

    for (int k = 0; k < NKI; k++) {
        cp_wait<1>();
        __syncthreads();
        const uint32_t st = sbase + (k & 1) * STG_B;

#pragma unroll
        for (int kk = 0; kk < 2; kk++) {
            uint32_t ah[4][4], al[4][4], bh[2][4], bl[2][4];
#pragma unroll
            for (int mt = 0; mt < 4; mt++) {
                int row = wm0 + mt * 16 + a_row_l;
                int c = kk * 2 + a_cl;
                uint32_t off = swz(row, c);
                ldm4(ah[mt][0], ah[mt][1], ah[mt][2], ah[mt][3],
                     st + OFF_AH + off);
                ldm4(al[mt][0], al[mt][1], al[mt][2], al[mt][3],
                     st + OFF_AL + off);
            }
#pragma unroll
            for (int ng = 0; ng < 2; ng++) {
                int row = wn0 + ng * 16 + b_row_l;
                int c = kk * 2 + b_cl;
                uint32_t off = swz(row, c);
                ldm4(bh[ng][0], bh[ng][1], bh[ng][2], bh[ng][3],
                     st + OFF_BH + off);
                ldm4(bl[ng][0], bl[ng][1], bl[ng][2], bl[ng][3],
                     st + OFF_BL + off);
            }
#pragma unroll
            for (int mt = 0; mt < 4; mt++) {
#pragma unroll
                for (int nt = 0; nt < 4; nt++) {
                    const int ng = nt >> 1, hb = (nt & 1) * 2;
                    mma16816(acc[mt][nt], ah[mt][0], ah[mt][1], ah[mt][2],
                             ah[mt][3], bh[ng][hb], bh[ng][hb + 1]);
                    mma16816(acc[mt][nt], ah[mt][0], ah[mt][1], ah[mt][2],
                             ah[mt][3], bl[ng][hb], bl[ng][hb + 1]);
                    mma16816(acc[mt][nt], al[mt][0], al[mt][1], al[mt][2],
                             al[mt][3], bh[ng][hb], bh[ng][hb + 1]);
                }
            }
        }
        __syncthreads();
        if (k + 2 < NKI)
            g_load_stage(sbase + (k & 1) * STG_B, Ah, Al, Bh, Bl,
                         m0, n0, (k + 2) * BK, tid);
        cp_commit();
    }

    // epilogue
    const int er = lane >> 2;
    const int ec = (lane & 3) * 2;
#pragma unroll
    for (int mt = 0; mt < 4; mt++) {
#pragma unroll
        for (int nt = 0; nt < 4; nt++) {
            float* p0 = C + (size_t)(m0 + wm0 + mt * 16 + er) * DD
                          + n0 + wn0 + nt * 8 + ec;
            float* p1 = p0 + 8 * DD;
            *(float2*)p0 = make_float2(acc[mt][nt][0], acc[mt][nt][1]);
            *(float2*)p1 = make_float2(acc[mt][nt][2], acc[mt][nt][3]);
        }
    }
}

// ============================================================
// Flash attention (fp32, f32x2 FFMA) — unchanged
// ============================================================
#define SM_STRIDE 68
#define SM_TILE   (64 * SM_STRIDE)

__global__ __launch_bounds__(128) void attn_kernel(
    const float* __restrict__ Q, const float* __restrict__ Kg,
    const float* __restrict__ V, const float* __restrict__ mask,
    float* __restrict__ O)
{
    extern __shared__ float smx[];
    float* Qt = smx;
    float* Kt = smx + SM_TILE;
    float* Vs = smx + 2 * SM_TILE;
    float* Pt = smx + 3 * SM_TILE;

    const int tid = threadIdx.x;
    const int q0 = blockIdx.x * 64;
    const int h = blockIdx.y;
    const int b = blockIdx.z;
    const int ty = tid >> 3;
    const int tx = tid & 7;

    {
        int r = tid >> 1;
        int e0 = (tid & 1) * 32;
        const float* src = Q + ((size_t)(b * LL + q0 + r)) * DD + h * DHH + e0;
#pragma unroll
        for (int c = 0; c < 8; c++) {
            float4 v4 = *(const float4*)(src + 4 * c);
            int e = e0 + 4 * c;
            Qt[(e + 0) * SM_STRIDE + r] = v4.x;
            Qt[(e + 1) * SM_STRIDE + r] = v4.y;
            Qt[(e + 2) * SM_STRIDE + r] = v4.z;
            Qt[(e + 3) * SM_STRIDE + r] = v4.w;
        }
    }

    float mrun[4], lrun[4];
    F2 o2[4][4];
#pragma unroll
    for (int i = 0; i < 4; i++) {
        mrun[i] = -INFINITY;
        lrun[i] = 0.f;
#pragma unroll
        for (int j = 0; j < 4; j++) o2[i][j].u = 0ull;
    }

    for (int kb = 0; kb < 16; kb++) {
        const int k0 = kb * 64;
        __syncthreads();
        {
            int r = tid >> 1;
            int e0 = (tid & 1) * 32;
            const float* ksrc = Kg + ((size_t)(b * LL + k0 + r)) * DD + h * DHH + e0;
            const float* vsrc = V + ((size_t)(b * LL + k0 + r)) * DD + h * DHH + e0;
#pragma unroll
            for (int c = 0; c < 8; c++) {
                float4 kv = *(const float4*)(ksrc + 4 * c);
                int e = e0 + 4 * c;
                Kt[(e + 0) * SM_STRIDE + r] = kv.x;
                Kt[(e + 1) * SM_STRIDE + r] = kv.y;
                Kt[(e + 2) * SM_STRIDE + r] = kv.z;
                Kt[(e + 3) * SM_STRIDE + r] = kv.w;
                *(float4*)(Vs + r * SM_STRIDE + e) = *(const float4*)(vsrc + 4 * c);
            }
        }
        __syncthreads();

        F2 s2[4][4];
#pragma unroll
        for (int i = 0; i < 4; i++)
#pragma unroll
            for (int j = 0; j < 4; j++) s2[i][j].u = 0ull;

#pragma unroll 16
        for (int e = 0; e < 64; e++) {
            float4 qv = *(const float4*)(Qt + e * SM_STRIDE + ty * 4);
            u64 k20 = *(const u64*)(Kt + e * SM_STRIDE + tx * 8 + 0);
            u64 k21 = *(const u64*)(Kt + e * SM_STRIDE + tx * 8 + 2);
            u64 k22 = *(const u64*)(Kt + e * SM_STRIDE + tx * 8 + 4);
            u64 k23 = *(const u64*)(Kt + e * SM_STRIDE + tx * 8 + 6);
            float qq[4] = {qv.x, qv.y, qv.z, qv.w};
#pragma unroll
            for (int ii = 0; ii < 4; ii++) {
                u64 a2 = pack2(qq[ii], qq[ii]);
                fma2(s2[ii][0].u, a2, k20);
                fma2(s2[ii][1].u, a2, k21);
                fma2(s2[ii][2].u, a2, k22);
                fma2(s2[ii][3].u, a2, k23);
            }
        }

#pragma unroll
        for (int ii = 0; ii < 4; ii++) {
            float sv[8];
            sv[0] = s2[ii][0].f.x; sv[1] = s2[ii][0].f.y;
            sv[2] = s2[ii][1].f.x; sv[3] = s2[ii][1].f.y;
            sv[4] = s2[ii][2].f.x; sv[5] = s2[ii][2].f.y;
            sv[6] = s2[ii][3].f.x; sv[7] = s2[ii][3].f.y;

            const float* mp = mask + (size_t)(q0 + ty * 4 + ii) * LL + k0 + tx * 8;
            float4 m4a = *(const float4*)mp;
            float4 m4b = *(const float4*)(mp + 4);
            float mm[8] = {m4a.x, m4a.y, m4a.z, m4a.w, m4b.x, m4b.y, m4b.z, m4b.w};
#pragma unroll
            for (int e = 0; e < 8; e++)
                sv[e] = (mm[e] != 0.f) ? sv[e] * 0.125f : -1.25e8f;

            float rmax = sv[0];
#pragma unroll
            for (int e = 1; e < 8; e++) rmax = fmaxf(rmax, sv[e]);
            rmax = fmaxf(rmax, __shfl_xor_sync(0xffffffffu, rmax, 1));
            rmax = fmaxf(rmax, __shfl_xor_sync(0xffffffffu, rmax, 2));
            rmax = fmaxf(rmax, __shfl_xor_sync(0xffffffffu, rmax, 4));

            float nm = fmaxf(mrun[ii], rmax);
            float corr = __expf(mrun[ii] - nm);
            mrun[ii] = nm;

            float rsum = 0.f;
#pragma unroll
            for (int e = 0; e < 8; e++) {
                float p = __expf(sv[e] - nm);
                sv[e] = p;
                rsum += p;
            }
            rsum += __shfl_xor_sync(0xffffffffu, rsum, 1);
            rsum += __shfl_xor_sync(0xffffffffu, rsum, 2);
            rsum += __shfl_xor_sync(0xffffffffu, rsum, 4);
            lrun[ii] = lrun[ii] * corr + rsum;

            u64 c2 = pack2(corr, corr);
#pragma unroll
            for (int j = 0; j < 4; j++) mul2(o2[ii][j].u, c2);

#pragma unroll
            for (int e = 0; e < 8; e++)
                Pt[(tx * 8 + e) * SM_STRIDE + ty * 4 + ii] = sv[e];
        }
        __syncthreads();

#pragma unroll 16
        for (int j = 0; j < 64; j++) {
            float4 pv = *(const float4*)(Pt + j * SM_STRIDE + ty * 4);
            u64 v20 = *(const u64*)(Vs + j * SM_STRIDE + tx * 8 + 0);
            u64 v21 = *(const u64*)(Vs + j * SM_STRIDE + tx * 8 + 2);
            u64 v22 = *(const u64*)(Vs + j * SM_STRIDE + tx * 8 + 4);
            u64 v23 = *(const u64*)(Vs + j * SM_STRIDE + tx * 8 + 6);
            float pp[4] = {pv.x, pv.y, pv.z, pv.w};
#pragma unroll
            for (int ii = 0; ii < 4; ii++) {
                u64 a2 = pack2(pp[ii], pp[ii]);
                fma2(o2[ii][0].u, a2, v20);
                fma2(o2[ii][1].u, a2, v21);
                fma2(o2[ii][2].u, a2, v22);
                fma2(o2[ii][3].u, a2, v23);
            }
        }
    }

#pragma unroll
    for (int ii = 0; ii < 4; ii++) {
        float inv = 1.f / lrun[ii];
        float* dst = O + ((size_t)(b * LL + q0 + ty * 4 + ii)) * DD + h * DHH + tx * 8;
        float4 c0 = make_float4(o2[ii][0].f.x * inv, o2[ii][0].f.y * inv,
                                o2[ii][1].f.x * inv, o2[ii][1].f.y * inv);
        float4 c1 = make_float4(o2[ii][2].f.x * inv, o2[ii][2].f.y * inv,
                                o2[ii][3].f.x * inv, o2[ii][3].f.y * inv);
        *(float4*)dst = c0;
        *(float4*)(dst + 4) = c1;
    }
}

// ============================================================
// Launch
// ============================================================
extern "C" void kernel_launch(void* const* d_in, const int* in_sizes, int n_in,
                              void* d_out, int out_size)
{
    const float* x    = (const float*)d_in[0];
    const float* mask = (const float*)d_in[1];
    const float* Wk   = (const float*)d_in[2];
    const float* Wv   = (const float*)d_in[3];
    const float* Wq   = (const float*)d_in[4];
    const float* Wo   = (const float*)d_in[5];
    float* out = (float*)d_out;

    float *gq, *gk, *gv, *ga;
    __nv_bfloat16 *xh, *xl, *ah, *al, *wh, *wl;
    cudaGetSymbolAddress((void**)&gq, g_q);
    cudaGetSymbolAddress((void**)&gk, g_k);
    cudaGetSymbolAddress((void**)&gv, g_v);
    cudaGetSymbolAddress((void**)&ga, g_a);
    cudaGetSymbolAddress((void**)&xh, g_xh);
    cudaGetSymbolAddress((void**)&xl, g_xl);
    cudaGetSymbolAddress((void**)&ah, g_ah);
    cudaGetSymbolAddress((void**)&al, g_al);
    cudaGetSymbolAddress((void**)&wh, g_wh);
    cudaGetSymbolAddress((void**)&wl, g_wl);

    static int attr_set = 0;
    const int attn_smem = 4 * SM_TILE * (int)sizeof(float);
    if (!attr_set) {
        cudaFuncSetAttribute(attn_kernel,
                             cudaFuncAttributeMaxDynamicSharedMemorySize, attn_smem);
        cudaFuncSetAttribute(gemm_mma_kernel,
                             cudaFuncAttributeMaxDynamicSharedMemorySize, GSMEM);
        attr_set = 1;
    }

    // 1) splits: x and the 4 weights (order: Wk, Wv, Wq, Wo)
    {
        int n4 = MM * DD / 4;
        split_kernel<<<(n4 + 255) / 256, 256>>>(
            (const float4*)x, (__nv_bfloat162*)xh, (__nv_bfloat162*)xl, n4);
        int w4 = DD * DD / 4;
        const float* ws[4] = {Wk, Wv, Wq, Wo};
        for (int i = 0; i < 4; i++) {
            split_kernel<<<(w4 + 255) / 256, 256>>>(
                (const float4*)ws[i],
                (__nv_bfloat162*)(wh + (size_t)i * DD * DD),
                (__nv_bfloat162*)(wl + (size_t)i * DD * DD), w4);
        }
    }

    // 2) projection GEMMs on tensor cores (mma.sync)
    dim3 ggrid(DD / 128, MM / 128);  // (8, 64)
    gemm_mma_kernel<<<ggrid, 256, GSMEM>>>(xh, xl,
        wh + (size_t)2 * DD * DD, wl + (size_t)2 * DD * DD, gq);  // Wq
    gemm_mma_kernel<<<ggrid, 256, GSMEM>>>(xh, xl,
        wh + (size_t)0 * DD * DD, wl + (size_t)0 * DD * DD, gk);  // Wk
    gemm_mma_kernel<<<ggrid, 256, GSMEM>>>(xh, xl,
        wh + (size_t)1 * DD * DD, wl + (size_t)1 * DD * DD, gv);  // Wv

    // 3) attention
    dim3 agrid(LL / 64, HH, BB);
    attn_kernel<<<agrid, 128, attn_smem>>>(gq, gk, gv, mask, ga);

    // 4) output projection
    {
        int n4 = MM * DD / 4;
        split_kernel<<<(n4 + 255) / 256, 256>>>(
            (const float4*)ga, (__nv_bfloat162*)ah, (__nv_bfloat162*)al, n4);
    }
    gemm_mma_kernel<<<ggrid, 256, GSMEM>>>(ah, al,
        wh + (size_t)3 * DD * DD, wl + (size_t)3 * DD * DD, out);  // Wo
}

// round 5
// speedup vs baseline: 3.1452x; 2.0611x over previous
#include <cuda_runtime.h>
#include <cuda_bf16.h>
#include <cuda_fp16.h>
#include <math.h>
#include <stdint.h>

#define BB  8
#define LL  1024
#define DD  1024
#define HH  16
#define DHH 64
#define MM  (BB * LL)

typedef unsigned long long u64;

// ---------------- device-global scratch ----------------
__device__ __nv_bfloat16 g_xh[MM * DD], g_xl[MM * DD];
__device__ __nv_bfloat16 g_wh[4][DD * DD], g_wl[4][DD * DD];
__device__ __half g_qh[MM * DD], g_ql[MM * DD];
__device__ __half g_kh[MM * DD], g_kl[MM * DD];
__device__ __half g_vh[MM * DD], g_vl[MM * DD];
__device__ __nv_bfloat16 g_ah[MM * DD], g_al[MM * DD];
__device__ float g_bias[LL * LL];

// ---------------- PTX helpers ----------------
__device__ __forceinline__ uint32_t s2u(const void* p) {
    uint32_t a;
    asm("{ .reg .u64 t; cvta.to.shared.u64 t, %1; cvt.u32.u64 %0, t; }"
        : "=r"(a) : "l"(p));
    return a;
}
__device__ __forceinline__ void cp16(uint32_t d, const void* s) {
    asm volatile("cp.async.cg.shared.global [%0], [%1], 16;" :: "r"(d), "l"(s));
}
__device__ __forceinline__ void cp_commit() {
    asm volatile("cp.async.commit_group;");
}
template <int N> __device__ __forceinline__ void cp_wait() {
    asm volatile("cp.async.wait_group %0;" :: "n"(N));
}
__device__ __forceinline__ void ldm4(uint32_t& r0, uint32_t& r1,
                                     uint32_t& r2, uint32_t& r3, uint32_t a) {
    asm volatile("ldmatrix.sync.aligned.m8n8.x4.shared.b16 {%0,%1,%2,%3}, [%4];"
                 : "=r"(r0), "=r"(r1), "=r"(r2), "=r"(r3) : "r"(a));
}
__device__ __forceinline__ void ldm4t(uint32_t& r0, uint32_t& r1,
                                      uint32_t& r2, uint32_t& r3, uint32_t a) {
    asm volatile("ldmatrix.sync.aligned.m8n8.x4.trans.shared.b16 {%0,%1,%2,%3}, [%4];"
                 : "=r"(r0), "=r"(r1), "=r"(r2), "=r"(r3) : "r"(a));
}
__device__ __forceinline__ void mma_bf16(float* c, const uint32_t* a,
                                         uint32_t b0, uint32_t b1) {
    asm volatile(
        "mma.sync.aligned.m16n8k16.row.col.f32.bf16.bf16.f32 "
        "{%0,%1,%2,%3}, {%4,%5,%6,%7}, {%8,%9}, {%0,%1,%2,%3};"
        : "+f"(c[0]), "+f"(c[1]), "+f"(c[2]), "+f"(c[3])
        : "r"(a[0]), "r"(a[1]), "r"(a[2]), "r"(a[3]), "r"(b0), "r"(b1));
}
__device__ __forceinline__ void mma_f16(float* c, uint32_t a0, uint32_t a1,
                                        uint32_t a2, uint32_t a3,
                                        uint32_t b0, uint32_t b1) {
    asm volatile(
        "mma.sync.aligned.m16n8k16.row.col.f32.f16.f16.f32 "
        "{%0,%1,%2,%3}, {%4,%5,%6,%7}, {%8,%9}, {%0,%1,%2,%3};"
        : "+f"(c[0]), "+f"(c[1]), "+f"(c[2]), "+f"(c[3])
        : "r"(a0), "r"(a1), "r"(a2), "r"(a3), "r"(b0), "r"(b1));
}
__device__ __forceinline__ float ex2f(float x) {
    float r;
    asm("ex2.approx.ftz.f32 %0, %1;" : "=f"(r) : "f"(x));
    return r;
}
__device__ __forceinline__ uint32_t packh2(float hi, float lo) {
    uint32_t r;
    asm("cvt.rn.f16x2.f32 %0, %1, %2;" : "=r"(r) : "f"(hi), "f"(lo));
    return r;
}
__device__ __forceinline__ float2 h2f2(uint32_t u) {
    __half2 h = *reinterpret_cast<__half2*>(&u);
    return __half22float2(h);
}

// ============================================================
// split fp32 -> bf16 hi/lo
// ============================================================
__global__ __launch_bounds__(256) void split_kernel(
    const float4* __restrict__ src,
    __nv_bfloat162* __restrict__ hi, __nv_bfloat162* __restrict__ lo, int n4)
{
    int i = blockIdx.x * blockDim.x + threadIdx.x;
    if (i >= n4) return;
    float4 v = src[i];
    __nv_bfloat16 hx = __float2bfloat16(v.x), hy = __float2bfloat16(v.y);
    __nv_bfloat16 hz = __float2bfloat16(v.z), hw = __float2bfloat16(v.w);
    hi[2 * i + 0] = __nv_bfloat162(hx, hy);
    hi[2 * i + 1] = __nv_bfloat162(hz, hw);
    lo[2 * i + 0] = __floats2bfloat162_rn(v.x - __bfloat162float(hx),
                                          v.y - __bfloat162float(hy));
    lo[2 * i + 1] = __floats2bfloat162_rn(v.z - __bfloat162float(hz),
                                          v.w - __bfloat162float(hw));
}

// ============================================================
// mask -> additive bias permuted into MMA fragment order
// ============================================================
__global__ __launch_bounds__(256) void bias_kernel(
    const float* __restrict__ mask, float* __restrict__ bias)
{
    int idx = blockIdx.x * blockDim.x + threadIdx.x;
    if (idx >= LL * LL) return;
    int j = idx & 3, nt = (idx >> 2) & 15, lane = (idx >> 6) & 31;
    int w = (idx >> 11) & 7, kb = (idx >> 14) & 7, qb = idx >> 17;
    int q = qb * 128 + w * 16 + (lane >> 2) + 8 * (j >> 1);
    int k = kb * 128 + nt * 8 + (lane & 3) * 2 + (j & 1);
    bias[idx] = (mask[q * LL + k] != 0.f) ? 0.f : -1.0e6f;
}

// ============================================================
// bf16-split GEMM (NT). mode 0: fp32 out. mode 1: f16 hi/lo out, scaled.
// ============================================================
#define BK 32
#define NKI (DD / BK)
#define MAT_B 8192
#define STG_B (4 * MAT_B)
#define OFF_AH 0
#define OFF_AL MAT_B
#define OFF_BH (2 * MAT_B)
#define OFF_BL (3 * MAT_B)
#define GSMEM (2 * STG_B)

__device__ __forceinline__ uint32_t swz(int row, int c) {
    return (uint32_t)(row * 64 + ((c ^ (row & 3)) << 4));
}

__device__ __forceinline__ void g_load_stage(
    uint32_t sbase,
    const __nv_bfloat16* __restrict__ Ah, const __nv_bfloat16* __restrict__ Al,
    const __nv_bfloat16* __restrict__ Bh, const __nv_bfloat16* __restrict__ Bl,
    int m0, int n0, int k0, int tid)
{
    const int r1 = tid >> 2, r2 = r1 + 64, c = tid & 3;
    const int kc = k0 + c * 8;
    const size_t a1 = (size_t)(m0 + r1) * DD + kc;
    const size_t a2 = (size_t)(m0 + r2) * DD + kc;
    const size_t b1 = (size_t)(n0 + r1) * DD + kc;
    const size_t b2 = (size_t)(n0 + r2) * DD + kc;
    const uint32_t s1 = swz(r1, c), s2 = swz(r2, c);
    cp16(sbase + OFF_AH + s1, Ah + a1);
    cp16(sbase + OFF_AH + s2, Ah + a2);
    cp16(sbase + OFF_AL + s1, Al + a1);
    cp16(sbase + OFF_AL + s2, Al + a2);
    cp16(sbase + OFF_BH + s1, Bh + b1);
    cp16(sbase + OFF_BH + s2, Bh + b2);
    cp16(sbase + OFF_BL + s1, Bl + b1);
    cp16(sbase + OFF_BL + s2, Bl + b2);
}

__global__ __launch_bounds__(256, 1) void gemm_mma_kernel(
    const __nv_bfloat16* __restrict__ Ah, const __nv_bfloat16* __restrict__ Al,
    const __nv_bfloat16* __restrict__ Bh, const __nv_bfloat16* __restrict__ Bl,
    float* __restrict__ Cf, __half* __restrict__ Ch, __half* __restrict__ Cl,
    float scale, int mode)
{
    extern __shared__ char smg[];
    const uint32_t sbase = s2u(smg);
    const int tid = threadIdx.x, wid = tid >> 5, lane = tid & 31;
    const int m0 = blockIdx.y * 128, n0 = blockIdx.x * 128;
    const int wm0 = (wid & 1) * 64, wn0 = (wid >> 1) * 32;

    float acc[4][4][4];
#pragma unroll
    for (int i = 0; i < 4; i++)
#pragma unroll
        for (int j = 0; j < 4; j++)
#pragma unroll
            for (int r = 0; r < 4; r++) acc[i][j][r] = 0.f;

    const int a_row_l = ((lane >> 3) & 1) * 8 + (lane & 7);
    const int a_cl = lane >> 4;
    const int b_row_l = (lane >> 4) * 8 + (lane & 7);
    const int b_cl = (lane >> 3) & 1;

    g_load_stage(sbase, Ah, Al, Bh, Bl, m0, n0, 0, tid);
    cp_commit();
    g_load_stage(sbase + STG_B, Ah, Al, Bh, Bl, m0, n0, BK, tid);
    cp_commit();

    for (int k = 0; k < NKI; k++) {
        cp_wait<1>();
        __syncthreads();
        const uint32_t st = sbase + (k & 1) * STG_B;
#pragma unroll
        for (int kk = 0; kk < 2; kk++) {
            uint32_t ah[4][4], al[4][4], bh[2][4], bl[2][4];
#pragma unroll
            for (int mt = 0; mt < 4; mt++) {
                uint32_t off = swz(wm0 + mt * 16 + a_row_l, kk * 2 + a_cl);
                ldm4(ah[mt][0], ah[mt][1], ah[mt][2], ah[mt][3], st + OFF_AH + off);
                ldm4(al[mt][0], al[mt][1], al[mt][2], al[mt][3], st + OFF_AL + off);
            }
#pragma unroll
            for (int ng = 0; ng < 2; ng++) {
                uint32_t off = swz(wn0 + ng * 16 + b_row_l, kk * 2 + b_cl);
                ldm4(bh[ng][0], bh[ng][1], bh[ng][2], bh[ng][3], st + OFF_BH + off);
                ldm4(bl[ng][0], bl[ng][1], bl[ng][2], bl[ng][3], st + OFF_BL + off);
            }
#pragma unroll
            for (int mt = 0; mt < 4; mt++)
#pragma unroll
                for (int nt = 0; nt < 4; nt++) {
                    const int ng = nt >> 1, hb = (nt & 1) * 2;
                    mma_bf16(acc[mt][nt], ah[mt], bh[ng][hb], bh[ng][hb + 1]);
                    mma_bf16(acc[mt][nt], ah[mt], bl[ng][hb], bl[ng][hb + 1]);
                    mma_bf16(acc[mt][nt], al[mt], bh[ng][hb], bh[ng][hb + 1]);
                }
        }
        __syncthreads();
        if (k + 2 < NKI)
            g_load_stage(sbase + (k & 1) * STG_B, Ah, Al, Bh, Bl,
                         m0, n0, (k + 2) * BK, tid);
        cp_commit();
    }

    const int er = lane >> 2, ec = (lane & 3) * 2;
#pragma unroll
    for (int mt = 0; mt < 4; mt++)
#pragma unroll
        for (int nt = 0; nt < 4; nt++) {
            size_t i0 = (size_t)(m0 + wm0 + mt * 16 + er) * DD + n0 + wn0 + nt * 8 + ec;
            size_t i1 = i0 + 8 * DD;
            if (mode == 0) {
                *(float2*)(Cf + i0) = make_float2(acc[mt][nt][0], acc[mt][nt][1]);
                *(float2*)(Cf + i1) = make_float2(acc[mt][nt][2], acc[mt][nt][3]);
            } else {
                float v0 = acc[mt][nt][0] * scale, v1 = acc[mt][nt][1] * scale;
                float v2 = acc[mt][nt][2] * scale, v3 = acc[mt][nt][3] * scale;
                __half h0 = __float2half_rn(v0), h1 = __float2half_rn(v1);
                __half h2 = __float2half_rn(v2), h3 = __float2half_rn(v3);
                *(__half2*)(Ch + i0) = __half2(h0, h1);
                *(__half2*)(Ch + i1) = __half2(h2, h3);
                *(__half2*)(Cl + i0) = __half2(__float2half_rn(v0 - __half2float(h0)),
                                               __float2half_rn(v1 - __half2float(h1)));
                *(__half2*)(Cl + i1) = __half2(__float2half_rn(v2 - __half2float(h2)),
                                               __float2half_rn(v3 - __half2float(h3)));
            }
        }
}

// ============================================================
// Tensor-core flash attention. CTA=(qb,h,b), 8 warps x 16 rows.
// ============================================================
#define A_QH 0
#define A_QL 16384
#define A_ST 32768
#define A_STGB 65536
#define A_KH 0
#define A_KL 16384
#define A_VH 32768
#define A_VL 49152
#define A_SMEM (A_ST + 2 * A_STGB)

__device__ __forceinline__ void a_load_q(
    uint32_t sb, const __half* qh, const __half* ql, int b, int q0, int h, int tid)
{
    const int row = tid >> 1, cb = (tid & 1) * 4;
    const size_t base = ((size_t)(b * LL + q0 + row)) * DD + h * DHH;
#pragma unroll
    for (int c = 0; c < 4; c++) {
        int ch = cb + c;
        uint32_t dst = (uint32_t)(row * 128 + ((ch ^ (row & 7)) << 4));
        cp16(sb + A_QH + dst, qh + base + ch * 8);
        cp16(sb + A_QL + dst, ql + base + ch * 8);
    }
}
__device__ __forceinline__ void a_load_kv(
    uint32_t stg, const __half* kh, const __half* kl,
    const __half* vh, const __half* vl, int b, int k0, int h, int tid)
{
    const int row = tid >> 1, cb = (tid & 1) * 4;
    const size_t base = ((size_t)(b * LL + k0 + row)) * DD + h * DHH;
#pragma unroll
    for (int c = 0; c < 4; c++) {
        int ch = cb + c;
        uint32_t dst = (uint32_t)(row * 128 + ((ch ^ (row & 7)) << 4));
        cp16(stg + A_KH + dst, kh + base + ch * 8);
        cp16(stg + A_KL + dst, kl + base + ch * 8);
        cp16(stg + A_VH + dst, vh + base + ch * 8);
        cp16(stg + A_VL + dst, vl + base + ch * 8);
    }
}

__global__ __launch_bounds__(256, 1) void attn_mma_kernel(
    const __half* __restrict__ qh, const __half* __restrict__ ql,
    const __half* __restrict__ kh, const __half* __restrict__ kl,
    const __half* __restrict__ vh, const __half* __restrict__ vl,
    const float* __restrict__ biasP,
    __nv_bfloat16* __restrict__ ah, __nv_bfloat16* __restrict__ al)
{
    extern __shared__ char sma[];
    const uint32_t sb = s2u(sma);
    const int tid = threadIdx.x, lane = tid & 31, w = tid >> 5;
    const int qb = blockIdx.x, h = blockIdx.y, b = blockIdx.z;
    const int q0 = qb * 128;

    a_load_q(sb, qh, ql, b, q0, h, tid);
    a_load_kv(sb + A_ST, kh, kl, vh, vl, b, 0, h, tid);
    cp_commit();
    cp_wait<0>();
    __syncthreads();

    uint32_t qfh[4][4], qfl[4][4];
    {
        const int arow = w * 16 + ((lane >> 3) & 1) * 8 + (lane & 7);
        const int acl = lane >> 4;
#pragma unroll
        for (int kc = 0; kc < 4; kc++) {
            int ch = kc * 2 + acl;
            uint32_t off = (uint32_t)(arow * 128 + ((ch ^ (arow & 7)) << 4));
            ldm4(qfh[kc][0], qfh[kc][1], qfh[kc][2], qfh[kc][3], sb + A_QH + off);
            ldm4(qfl[kc][0], qfl[kc][1], qfl[kc][2], qfl[kc][3], sb + A_QL + off);
        }
    }

    float acc_o[8][4];
#pragma unroll
    for (int i = 0; i < 8; i++)
#pragma unroll
        for (int j = 0; j < 4; j++) acc_o[i][j] = 0.f;
    float m0r = -1e30f, m1r = -1e30f, l0r = 0.f, l1r = 0.f;

    const float* bp = biasP + (((size_t)(qb * 8) * 8 + w) * 32 + lane) * 64;
    const int b_row_l = (lane >> 4) * 8 + (lane & 7);
    const int b_cl = (lane >> 3) & 1;
    const int v_row_l = ((lane >> 3) & 1) * 8 + (lane & 7);
    const int v_cl = lane >> 4;

    for (int kb = 0; kb < 8; kb++) {
        cp_wait<0>();
        __syncthreads();
        if (kb + 1 < 8) {
            a_load_kv(sb + A_ST + ((kb + 1) & 1) * A_STGB,
                      kh, kl, vh, vl, b, (kb + 1) * 128, h, tid);
            cp_commit();
        }
        const uint32_t stg = sb + A_ST + (kb & 1) * A_STGB;

        float s[16][4];
#pragma unroll
        for (int i = 0; i < 16; i++)
#pragma unroll
            for (int j = 0; j < 4; j++) s[i][j] = 0.f;

#pragma unroll
        for (int g = 0; g < 8; g++)
#pragma unroll
            for (int kc = 0; kc < 4; kc++) {
                int row = g * 16 + b_row_l, ch = kc * 2 + b_cl;
                uint32_t off = (uint32_t)(row * 128 + ((ch ^ (row & 7)) << 4));
                uint32_t k4h[4], k4l[4];
                ldm4(k4h[0], k4h[1], k4h[2], k4h[3], stg + A_KH + off);
                ldm4(k4l[0], k4l[1], k4l[2], k4l[3], stg + A_KL + off);
                mma_f16(s[2*g],   qfh[kc][0], qfh[kc][1], qfh[kc][2], qfh[kc][3], k4h[0], k4h[1]);
                mma_f16(s[2*g+1], qfh[kc][0], qfh[kc][1], qfh[kc][2], qfh[kc][3], k4h[2], k4h[3]);
                mma_f16(s[2*g],   qfh[kc][0], qfh[kc][1], qfh[kc][2], qfh[kc][3], k4l[0], k4l[1]);
                mma_f16(s[2*g+1], qfh[kc][0], qfh[kc][1], qfh[kc][2], qfh[kc][3], k4l[2], k4l[3]);
                mma_f16(s[2*g],   qfl[kc][0], qfl[kc][1], qfl[kc][2], qfl[kc][3], k4h[0], k4h[1]);
                mma_f16(s[2*g+1], qfl[kc][0], qfl[kc][1], qfl[kc][2], qfl[kc][3], k4h[2], k4h[3]);
            }

        const float4* b4 = (const float4*)(bp + (size_t)kb * 16384);
        float mx0 = -1e30f, mx1 = -1e30f;
#pragma unroll
        for (int nt = 0; nt < 16; nt++) {
            float4 bb = b4[nt];
            s[nt][0] += bb.x; s[nt][1] += bb.y;
            s[nt][2] += bb.z; s[nt][3] += bb.w;
            mx0 = fmaxf(mx0, fmaxf(s[nt][0], s[nt][1]));
            mx1 = fmaxf(mx1, fmaxf(s[nt][2], s[nt][3]));
        }
        mx0 = fmaxf(mx0, __shfl_xor_sync(~0u, mx0, 1));
        mx0 = fmaxf(mx0, __shfl_xor_sync(~0u, mx0, 2));
        mx1 = fmaxf(mx1, __shfl_xor_sync(~0u, mx1, 1));
        mx1 = fmaxf(mx1, __shfl_xor_sync(~0u, mx1, 2));
        float mn0 = fmaxf(m0r, mx0), mn1 = fmaxf(m1r, mx1);
        float c0 = ex2f(m0r - mn0), c1 = ex2f(m1r - mn1);
        m0r = mn0; m1r = mn1;

        float ls0 = 0.f, ls1 = 0.f;
#pragma unroll
        for (int nt = 0; nt < 16; nt++) {
            s[nt][0] = ex2f(s[nt][0] - mn0);
            s[nt][1] = ex2f(s[nt][1] - mn0);
            s[nt][2] = ex2f(s[nt][2] - mn1);
            s[nt][3] = ex2f(s[nt][3] - mn1);
            ls0 += s[nt][0] + s[nt][1];
            ls1 += s[nt][2] + s[nt][3];
        }
        ls0 += __shfl_xor_sync(~0u, ls0, 1);
        ls0 += __shfl_xor_sync(~0u, ls0, 2);
        ls1 += __shfl_xor_sync(~0u, ls1, 1);
        ls1 += __shfl_xor_sync(~0u, ls1, 2);
        l0r = l0r * c0 + ls0;
        l1r = l1r * c1 + ls1;
#pragma unroll
        for (int i = 0; i < 8; i++) {
            acc_o[i][0] *= c0; acc_o[i][1] *= c0;
            acc_o[i][2] *= c1; acc_o[i][3] *= c1;
        }

#pragma unroll
        for (int kc = 0; kc < 8; kc++) {
            uint32_t ph0 = packh2(s[2*kc][1],   s[2*kc][0]);
            uint32_t ph1 = packh2(s[2*kc][3],   s[2*kc][2]);
            uint32_t ph2 = packh2(s[2*kc+1][1], s[2*kc+1][0]);
            uint32_t ph3 = packh2(s[2*kc+1][3], s[2*kc+1][2]);
            float2 f0 = h2f2(ph0), f1 = h2f2(ph1), f2 = h2f2(ph2), f3 = h2f2(ph3);
            uint32_t pl0 = packh2(s[2*kc][1] - f0.y,   s[2*kc][0] - f0.x);
            uint32_t pl1 = packh2(s[2*kc][3] - f1.y,   s[2*kc][2] - f1.x);
            uint32_t pl2 = packh2(s[2*kc+1][1] - f2.y, s[2*kc+1][0] - f2.x);
            uint32_t pl3 = packh2(s[2*kc+1][3] - f3.y, s[2*kc+1][2] - f3.x);
            int vrow = kc * 16 + v_row_l;
#pragma unroll
            for (int x4 = 0; x4 < 4; x4++) {
                int ch = x4 * 2 + v_cl;
                uint32_t off = (uint32_t)(vrow * 128 + ((ch ^ (vrow & 7)) << 4));
                uint32_t v4h[4], v4l[4];
                ldm4t(v4h[0], v4h[1], v4h[2], v4h[3], stg + A_VH + off);
                ldm4t(v4l[0], v4l[1], v4l[2], v4l[3], stg + A_VL + off);
                mma_f16(acc_o[2*x4],   ph0, ph1, ph2, ph3, v4h[0], v4h[1]);
                mma_f16(acc_o[2*x4+1], ph0, ph1, ph2, ph3, v4h[2], v4h[3]);
                mma_f16(acc_o[2*x4],   pl0, pl1, pl2, pl3, v4h[0], v4h[1]);
                mma_f16(acc_o[2*x4+1], pl0, pl1, pl2, pl3, v4h[2], v4h[3]);
                mma_f16(acc_o[2*x4],   ph0, ph1, ph2, ph3, v4l[0], v4l[1]);
                mma_f16(acc_o[2*x4+1], ph0, ph1, ph2, ph3, v4l[2], v4l[3]);
            }
        }
    }

    // epilogue: normalize, bf16 hi/lo split, store
    const float inv0 = 1.f / l0r, inv1 = 1.f / l1r;
    const int r0 = q0 + w * 16 + (lane >> 2);
#pragma unroll
    for (int nt = 0; nt < 8; nt++) {
        int col = h * DHH + nt * 8 + (lane & 3) * 2;
        size_t i0 = (size_t)(b * LL + r0) * DD + col;
        size_t i1 = i0 + 8 * DD;
        float v0 = acc_o[nt][0] * inv0, v1 = acc_o[nt][1] * inv0;
        float v2 = acc_o[nt][2] * inv1, v3 = acc_o[nt][3] * inv1;
        __nv_bfloat16 h0 = __float2bfloat16(v0), h1 = __float2bfloat16(v1);
        __nv_bfloat16 h2 = __float2bfloat16(v2), h3 = __float2bfloat16(v3);
        *(__nv_bfloat162*)(ah + i0) = __nv_bfloat162(h0, h1);
        *(__nv_bfloat162*)(ah + i1) = __nv_bfloat162(h2, h3);
        *(__nv_bfloat162*)(al + i0) =
            __floats2bfloat162_rn(v0 - __bfloat162float(h0), v1 - __bfloat162float(h1));
        *(__nv_bfloat162*)(al + i1) =
            __floats2bfloat162_rn(v2 - __bfloat162float(h2), v3 - __bfloat162float(h3));
    }
}

// ============================================================
// Launch
// ============================================================
extern "C" void kernel_launch(void* const* d_in, const int* in_sizes, int n_in,
                              void* d_out, int out_size)
{
    const float* x    = (const float*)d_in[0];
    const float* mask = (const float*)d_in[1];
    const float* Wk   = (const float*)d_in[2];
    const float* Wv   = (const float*)d_in[3];
    const float* Wq   = (const float*)d_in[4];
    const float* Wo   = (const float*)d_in[5];
    float* out = (float*)d_out;

    __nv_bfloat16 *xh, *xl, *ah, *al, *wh, *wl;
    __half *qh, *ql, *kh, *kl, *vh, *vl;
    float* bias;
    cudaGetSymbolAddress((void**)&xh, g_xh);
    cudaGetSymbolAddress((void**)&xl, g_xl);
    cudaGetSymbolAddress((void**)&ah, g_ah);
    cudaGetSymbolAddress((void**)&al, g_al);
    cudaGetSymbolAddress((void**)&wh, g_wh);
    cudaGetSymbolAddress((void**)&wl, g_wl);
    cudaGetSymbolAddress((void**)&qh, g_qh);
    cudaGetSymbolAddress((void**)&ql, g_ql);
    cudaGetSymbolAddress((void**)&kh, g_kh);
    cudaGetSymbolAddress((void**)&kl, g_kl);
    cudaGetSymbolAddress((void**)&vh, g_vh);
    cudaGetSymbolAddress((void**)&vl, g_vl);
    cudaGetSymbolAddress((void**)&bias, g_bias);

    static int attr_set = 0;
    if (!attr_set) {
        cudaFuncSetAttribute(gemm_mma_kernel,
                             cudaFuncAttributeMaxDynamicSharedMemorySize, GSMEM);
        cudaFuncSetAttribute(attn_mma_kernel,
                             cudaFuncAttributeMaxDynamicSharedMemorySize, A_SMEM);
        attr_set = 1;
    }

    const float SCALE_Q = 0.125f * 1.44269504088896341f;

    {
        int n4 = MM * DD / 4;
        split_kernel<<<(n4 + 255) / 256, 256>>>(
            (const float4*)x, (__nv_bfloat162*)xh, (__nv_bfloat162*)xl, n4);
        int w4 = DD * DD / 4;
        const float* ws[4] = {Wk, Wv, Wq, Wo};
        for (int i = 0; i < 4; i++)
            split_kernel<<<(w4 + 255) / 256, 256>>>(
                (const float4*)ws[i],
                (__nv_bfloat162*)(wh + (size_t)i * DD * DD),
                (__nv_bfloat162*)(wl + (size_t)i * DD * DD), w4);
        bias_kernel<<<(LL * LL) / 256, 256>>>(mask, bias);
    }

    dim3 ggrid(DD / 128, MM / 128);
    gemm_mma_kernel<<<ggrid, 256, GSMEM>>>(xh, xl,
        wh + (size_t)2 * DD * DD, wl + (size_t)2 * DD * DD,
        nullptr, qh, ql, SCALE_Q, 1);  // Q (pre-scaled)
    gemm_mma_kernel<<<ggrid, 256, GSMEM>>>(xh, xl,
        wh + (size_t)0 * DD * DD, wl + (size_t)0 * DD * DD,
        nullptr, kh, kl, 1.0f, 1);     // K
    gemm_mma_kernel<<<ggrid, 256, GSMEM>>>(xh, xl,
        wh + (size_t)1 * DD * DD, wl + (size_t)1 * DD * DD,
        nullptr, vh, vl, 1.0f, 1);     // V

    dim3 agrid(LL / 128, HH, BB);
    attn_mma_kernel<<<agrid, 256, A_SMEM>>>(qh, ql, kh, kl, vh, vl, bias, ah, al);

    gemm_mma_kernel<<<ggrid, 256, GSMEM>>>(ah, al,
        wh + (size_t)3 * DD * DD, wl + (size_t)3 * DD * DD,
        out, nullptr, nullptr, 1.0f, 0);  // Wo
}